// round 1
// baseline (speedup 1.0000x reference)
#include <cuda_runtime.h>
#include <math.h>

// Scratch: repacked class boxes. Row = 64 floats (256B, line-aligned).
// Layout per row: for k in 0..24: f[2k]=lo_k, f[2k+1]=hi_k ; f[50]=s ; f[51]=b ; rest pad.
// loss = b - inter_area * s  reproduces:
//   area==0      -> b=0, s=0          -> loss 0
//   isinf(area)  -> b=1, s=1/20000    -> 1 - inter/(2*EMBEDDING_BOUND)
//   else         -> b=1, s=1/area     -> 1 - inter/area
#define MAX_CLASSES 100000
__device__ float g_rows[(size_t)MAX_CLASSES * 64];
__device__ double g_acc;

__global__ void repack_kernel(const float* __restrict__ emb, int n_classes)
{
    int i = blockIdx.x * blockDim.x + threadIdx.x;
    if (blockIdx.x == 0 && threadIdx.x == 0) g_acc = 0.0;
    if (i >= n_classes) return;

    const float* r = emb + (size_t)i * 50;
    float f[52];
    float area = 1.0f;
#pragma unroll
    for (int k = 0; k < 25; k++) {
        float c = r[k];
        float o = fabsf(r[25 + k]);
        f[2 * k]     = c - o;
        f[2 * k + 1] = c + o;
        area *= 2.0f * o;
    }
    float s, b;
    if (area == 0.0f)      { s = 0.0f;            b = 0.0f; }
    else if (isinf(area))  { s = 1.0f / 20000.0f; b = 1.0f; }
    else                   { s = 1.0f / area;     b = 1.0f; }
    f[50] = s;
    f[51] = b;

    float4* out = (float4*)(g_rows + (size_t)i * 64);
#pragma unroll
    for (int j = 0; j < 13; j++)
        out[j] = make_float4(f[4 * j], f[4 * j + 1], f[4 * j + 2], f[4 * j + 3]);
}

__global__ __launch_bounds__(256)
void pairs_kernel(const int2* __restrict__ nf1, int n_pairs)
{
    int i = blockIdx.x * blockDim.x + threadIdx.x;
    float val = 0.0f;

    if (i < n_pairs) {
        int2 p = nf1[i];
        const float4* __restrict__ A = (const float4*)(g_rows + (size_t)p.x * 64);
        const float4* __restrict__ B = (const float4*)(g_rows + (size_t)p.y * 64);

        float4 qa[13], qb[13];
#pragma unroll
        for (int j = 0; j < 13; j++) qa[j] = __ldg(A + j);
#pragma unroll
        for (int j = 0; j < 13; j++) qb[j] = __ldg(B + j);

        float prod = 1.0f;
#pragma unroll
        for (int j = 0; j < 12; j++) {
            // dims 2j and 2j+1: (lo,hi,lo,hi) in (x,y,z,w)
            float w0 = fminf(qa[j].y, qb[j].y) - fmaxf(qa[j].x, qb[j].x);
            float w1 = fminf(qa[j].w, qb[j].w) - fmaxf(qa[j].z, qb[j].z);
            prod *= fmaxf(w0, 0.0f);
            prod *= fmaxf(w1, 0.0f);
        }
        // dim 24 in qa[12].(x,y); s,b in qa[12].(z,w)
        float w24 = fminf(qa[12].y, qb[12].y) - fmaxf(qa[12].x, qb[12].x);
        prod *= fmaxf(w24, 0.0f);

        float loss = qa[12].w - prod * qa[12].z;   // b - inter * s
        float rl = fmaxf(loss, 0.0f);
        val = rl * rl;
    }

    // warp reduce
#pragma unroll
    for (int off = 16; off > 0; off >>= 1)
        val += __shfl_down_sync(0xFFFFFFFFu, val, off);

    __shared__ float sm[8];
    int lane = threadIdx.x & 31;
    int wid  = threadIdx.x >> 5;
    if (lane == 0) sm[wid] = val;
    __syncthreads();
    if (wid == 0) {
        float v = (lane < (blockDim.x >> 5)) ? sm[lane] : 0.0f;
#pragma unroll
        for (int off = 4; off > 0; off >>= 1)
            v += __shfl_down_sync(0xFFFFFFFFu, v, off);
        if (lane == 0)
            atomicAdd(&g_acc, (double)v);
    }
}

__global__ void finish_kernel(float* out)
{
    out[0] = (float)sqrt(g_acc);
}

extern "C" void kernel_launch(void* const* d_in, const int* in_sizes, int n_in,
                              void* d_out, int out_size)
{
    const float* class_embeds = (const float*)d_in[0];
    const int2*  nf1          = (const int2*)d_in[1];
    int n_classes = in_sizes[0] / 50;
    int n_pairs   = in_sizes[1] / 2;

    repack_kernel<<<(n_classes + 127) / 128, 128>>>(class_embeds, n_classes);
    pairs_kernel<<<(n_pairs + 255) / 256, 256>>>(nf1, n_pairs);
    finish_kernel<<<1, 1>>>((float*)d_out);
}

// round 2
// speedup vs baseline: 1.7465x; 1.7465x over previous
#include <cuda_runtime.h>
#include <math.h>

// Repacked class boxes. Row = 64 floats (256B, line-aligned).
// f[2k]=lo_k, f[2k+1]=hi_k (k=0..24); f[50]=s; f[51]=b; rest pad.
// loss = b - inter_area * s reproduces the reference's 3-way where().
#define MAX_CLASSES 100000
__device__ float g_rows[(size_t)MAX_CLASSES * 64];
__device__ double g_acc;

#define ROWS_PER_BLOCK 128

__global__ __launch_bounds__(256)
void repack_kernel(const float* __restrict__ emb, int n_classes)
{
    __shared__ float sm[ROWS_PER_BLOCK * 50];
    if (blockIdx.x == 0 && threadIdx.x == 0) g_acc = 0.0;

    int r0 = blockIdx.x * ROWS_PER_BLOCK;
    int nrows = n_classes - r0;
    if (nrows > ROWS_PER_BLOCK) nrows = ROWS_PER_BLOCK;
    int nflt = nrows * 50;
    const float* src = emb + (size_t)r0 * 50;

    // r0 is a multiple of 128 -> byte offset r0*200 is 128B-aligned.
    if ((((size_t)src) & 15) == 0 && (nflt & 3) == 0) {
        const float4* s4 = (const float4*)src;
        float4* d4 = (float4*)sm;
        int n4 = nflt >> 2;
        for (int i = threadIdx.x; i < n4; i += blockDim.x) d4[i] = s4[i];
    } else {
        for (int i = threadIdx.x; i < nflt; i += blockDim.x) sm[i] = src[i];
    }
    __syncthreads();

    int lr = threadIdx.x;
    if (lr < nrows) {
        const float* r = sm + lr * 50;
        float f[52];
        float area = 1.0f;
#pragma unroll
        for (int k = 0; k < 25; k++) {
            float c = r[k];
            float o = fabsf(r[25 + k]);
            f[2 * k]     = c - o;
            f[2 * k + 1] = c + o;
            area *= 2.0f * o;
        }
        float s, b;
        if (area == 0.0f)      { s = 0.0f;            b = 0.0f; }
        else if (isinf(area))  { s = 1.0f / 20000.0f; b = 1.0f; }
        else                   { s = 1.0f / area;     b = 1.0f; }
        f[50] = s;
        f[51] = b;

        float4* out = (float4*)(g_rows + (size_t)(r0 + lr) * 64);
#pragma unroll
        for (int j = 0; j < 13; j++)
            out[j] = make_float4(f[4 * j], f[4 * j + 1], f[4 * j + 2], f[4 * j + 3]);
    }
}

// 8 lanes cooperate per pair: lane g loads float4 g and g+8 of each row,
// so each warp-wide LDG.128 touches 4 cache lines instead of 32.
__global__ __launch_bounds__(256)
void pairs_kernel(const int2* __restrict__ nf1, int n_pairs)
{
    int tid  = blockIdx.x * blockDim.x + threadIdx.x;
    int pair = tid >> 3;
    int g    = tid & 7;
    bool live = (pair < n_pairs);
    int pe = live ? pair : (n_pairs - 1);   // clamp: keep all lanes convergent

    int2 p = nf1[pe];
    const float4* A = (const float4*)(g_rows + (size_t)p.x * 64);
    const float4* B = (const float4*)(g_rows + (size_t)p.y * 64);

    // first line: float4 index g covers bytes 0..127 exactly
    float4 a1 = __ldg(A + g);
    float4 b1 = __ldg(B + g);
    float w0 = fminf(a1.y, b1.y) - fmaxf(a1.x, b1.x);
    float w1 = fminf(a1.w, b1.w) - fmaxf(a1.z, b1.z);
    float prod = fmaxf(w0, 0.0f) * fmaxf(w1, 0.0f);

    float s = 0.0f, b = 0.0f;
    int j2 = g + 8;
    if (j2 <= 12) {
        float4 a2 = __ldg(A + j2);
        float4 b2 = __ldg(B + j2);
        if (j2 < 12) {
            float u0 = fminf(a2.y, b2.y) - fmaxf(a2.x, b2.x);
            float u1 = fminf(a2.w, b2.w) - fmaxf(a2.z, b2.z);
            prod *= fmaxf(u0, 0.0f) * fmaxf(u1, 0.0f);
        } else {
            float u0 = fminf(a2.y, b2.y) - fmaxf(a2.x, b2.x);
            prod *= fmaxf(u0, 0.0f);
            s = a2.z;   // 1/area (or 1/20000, or 0)
            b = a2.w;   // 1 (or 0)
        }
    }

    // multiply-reduce across the 8-lane group
    prod *= __shfl_xor_sync(0xFFFFFFFFu, prod, 1);
    prod *= __shfl_xor_sync(0xFFFFFFFFu, prod, 2);
    prod *= __shfl_xor_sync(0xFFFFFFFFu, prod, 4);

    float val = 0.0f;
    if (g == 4 && live) {
        float loss = b - prod * s;
        float rl = fmaxf(loss, 0.0f);
        val = rl * rl;
    }

    // warp reduce (sum)
#pragma unroll
    for (int off = 16; off > 0; off >>= 1)
        val += __shfl_down_sync(0xFFFFFFFFu, val, off);

    __shared__ float smred[8];
    int lane = threadIdx.x & 31;
    int wid  = threadIdx.x >> 5;
    if (lane == 0) smred[wid] = val;
    __syncthreads();
    if (wid == 0) {
        float v = (lane < (blockDim.x >> 5)) ? smred[lane] : 0.0f;
#pragma unroll
        for (int off = 4; off > 0; off >>= 1)
            v += __shfl_down_sync(0xFFFFFFFFu, v, off);
        if (lane == 0)
            atomicAdd(&g_acc, (double)v);
    }
}

__global__ void finish_kernel(float* out)
{
    out[0] = (float)sqrt(g_acc);
}

extern "C" void kernel_launch(void* const* d_in, const int* in_sizes, int n_in,
                              void* d_out, int out_size)
{
    const float* class_embeds = (const float*)d_in[0];
    const int2*  nf1          = (const int2*)d_in[1];
    int n_classes = in_sizes[0] / 50;
    int n_pairs   = in_sizes[1] / 2;

    repack_kernel<<<(n_classes + ROWS_PER_BLOCK - 1) / ROWS_PER_BLOCK, 256>>>(class_embeds, n_classes);

    long long threads = (long long)n_pairs * 8;
    int grid = (int)((threads + 255) / 256);
    pairs_kernel<<<grid, 256>>>(nf1, n_pairs);

    finish_kernel<<<1, 1>>>((float*)d_out);
}

// round 3
// speedup vs baseline: 3.2924x; 1.8851x over previous
#include <cuda_runtime.h>
#include <math.h>

// Repacked class boxes. Row = 64 floats (256B, line-aligned).
// f[2k]=lo_k, f[2k+1]=hi_k (k=0..24); f[50]=s; f[51]=b; rest pad.
// loss = b - inter_area * s reproduces the reference's 3-way where().
#define MAX_CLASSES 100000
__device__ float g_rows[(size_t)MAX_CLASSES * 64];
__device__ double g_acc;

// 8 lanes per class row. Lane g produces output float4 j=g (dims 2g,2g+1)
// and, for g<=4, float4 j=g+8 (dims 16+2g,17+2g; g==4: dim 24 + s,b).
__global__ __launch_bounds__(256)
void repack_kernel(const float* __restrict__ emb, int n_classes)
{
    int tid = blockIdx.x * blockDim.x + threadIdx.x;
    if (tid == 0) g_acc = 0.0;
    int row = tid >> 3;
    int g   = tid & 7;
    bool live = (row < n_classes);
    int re = live ? row : (n_classes - 1);

    const float* r = emb + (size_t)re * 50;

    // centers at floats [2g, 2g+1]: byte offset re*200 + 8g -> 8B aligned
    float2 c1 = *(const float2*)(r + 2 * g);
    float o1x = fabsf(r[25 + 2 * g]);       // offsets: 4B-aligned only
    float o1y = fabsf(r[26 + 2 * g]);
    float4 out1 = make_float4(c1.x - o1x, c1.x + o1x, c1.y - o1y, c1.y + o1y);
    float part = (2.0f * o1x) * (2.0f * o1y);

    float4 out2 = make_float4(0.f, 0.f, 0.f, 0.f);
    if (g <= 3) {
        float2 c2 = *(const float2*)(r + 16 + 2 * g);   // re*200+64+8g -> aligned
        float o2x = fabsf(r[41 + 2 * g]);
        float o2y = fabsf(r[42 + 2 * g]);
        out2 = make_float4(c2.x - o2x, c2.x + o2x, c2.y - o2y, c2.y + o2y);
        part *= (2.0f * o2x) * (2.0f * o2y);
    } else if (g == 4) {
        float c24 = r[24];
        float o24 = fabsf(r[49]);
        out2.x = c24 - o24;
        out2.y = c24 + o24;
        part *= 2.0f * o24;
    }

    // area = product across the 8-lane group
    part *= __shfl_xor_sync(0xFFFFFFFFu, part, 1);
    part *= __shfl_xor_sync(0xFFFFFFFFu, part, 2);
    part *= __shfl_xor_sync(0xFFFFFFFFu, part, 4);

    if (g == 4) {
        float s, b;
        if (part == 0.0f)      { s = 0.0f;            b = 0.0f; }
        else if (isinf(part))  { s = 1.0f / 20000.0f; b = 1.0f; }
        else                   { s = 1.0f / part;     b = 1.0f; }
        out2.z = s;
        out2.w = b;
    }

    if (live) {
        float4* out = (float4*)(g_rows + (size_t)re * 64);
        out[g] = out1;
        if (g <= 4) out[8 + g] = out2;
    }
}

// 8 lanes per pair, grid-stride with uniform trip count (all shfl groups stay
// converged). One double atomic per block.
__global__ __launch_bounds__(256)
void pairs_kernel(const int2* __restrict__ nf1, int n_pairs, int n_groups, int n_iter)
{
    int tid   = blockIdx.x * blockDim.x + threadIdx.x;
    int group = tid >> 3;
    int g     = tid & 7;
    int j2    = g + 8;

    float acc = 0.0f;

    for (int it = 0; it < n_iter; it++) {
        int pair = group + it * n_groups;
        bool live = (pair < n_pairs);
        int pe = live ? pair : (n_pairs - 1);

        int2 p = __ldg(nf1 + pe);
        const float4* A = (const float4*)(g_rows + (size_t)p.x * 64);
        const float4* B = (const float4*)(g_rows + (size_t)p.y * 64);

        float4 a1 = __ldg(A + g);
        float4 b1 = __ldg(B + g);
        float w0 = fminf(a1.y, b1.y) - fmaxf(a1.x, b1.x);
        float w1 = fminf(a1.w, b1.w) - fmaxf(a1.z, b1.z);
        float prod = fmaxf(w0, 0.0f) * fmaxf(w1, 0.0f);

        float s = 0.0f, b = 0.0f;
        if (j2 <= 12) {
            float4 a2 = __ldg(A + j2);
            float4 b2 = __ldg(B + j2);
            if (j2 < 12) {
                float u0 = fminf(a2.y, b2.y) - fmaxf(a2.x, b2.x);
                float u1 = fminf(a2.w, b2.w) - fmaxf(a2.z, b2.z);
                prod *= fmaxf(u0, 0.0f) * fmaxf(u1, 0.0f);
            } else {
                float u0 = fminf(a2.y, b2.y) - fmaxf(a2.x, b2.x);
                prod *= fmaxf(u0, 0.0f);
                s = a2.z;   // 1/area (or 1/20000, or 0)
                b = a2.w;   // 1 (or 0)
            }
        }

        prod *= __shfl_xor_sync(0xFFFFFFFFu, prod, 1);
        prod *= __shfl_xor_sync(0xFFFFFFFFu, prod, 2);
        prod *= __shfl_xor_sync(0xFFFFFFFFu, prod, 4);

        if (g == 4 && live) {
            float loss = b - prod * s;
            float rl = fmaxf(loss, 0.0f);
            acc += rl * rl;
        }
    }

    // warp reduce (only g==4 lanes carry nonzero acc; summing all is correct)
#pragma unroll
    for (int off = 16; off > 0; off >>= 1)
        acc += __shfl_down_sync(0xFFFFFFFFu, acc, off);

    __shared__ float smred[8];
    int lane = threadIdx.x & 31;
    int wid  = threadIdx.x >> 5;
    if (lane == 0) smred[wid] = acc;
    __syncthreads();
    if (wid == 0) {
        float v = (lane < (blockDim.x >> 5)) ? smred[lane] : 0.0f;
#pragma unroll
        for (int off = 4; off > 0; off >>= 1)
            v += __shfl_down_sync(0xFFFFFFFFu, v, off);
        if (lane == 0)
            atomicAdd(&g_acc, (double)v);
    }
}

__global__ void finish_kernel(float* out)
{
    out[0] = (float)sqrt(g_acc);
}

extern "C" void kernel_launch(void* const* d_in, const int* in_sizes, int n_in,
                              void* d_out, int out_size)
{
    const float* class_embeds = (const float*)d_in[0];
    const int2*  nf1          = (const int2*)d_in[1];
    int n_classes = in_sizes[0] / 50;
    int n_pairs   = in_sizes[1] / 2;

    {
        long long threads = (long long)n_classes * 8;
        int grid = (int)((threads + 255) / 256);
        repack_kernel<<<grid, 256>>>(class_embeds, n_classes);
    }

    {
        const int grid = 2368;              // 16 blocks/SM worth of work queue
        const int n_groups = grid * 256 / 8;
        int n_iter = (n_pairs + n_groups - 1) / n_groups;
        pairs_kernel<<<grid, 256>>>(nf1, n_pairs, n_groups, n_iter);
    }

    finish_kernel<<<1, 1>>>((float*)d_out);
}